// round 4
// baseline (speedup 1.0000x reference)
#include <cuda_runtime.h>
#include <cstdint>

#define NB    8
#define NPB   8192
#define FDIM  64
#define MQ    2048
#define KNN   32
#define CDIM  128
#define R2C   0.01f
#define NROWS (NB*NPB)
#define CAP   256

// scratch (device globals — no allocation allowed)
__device__ float g_xw[(size_t)NROWS * CDIM];   // x @ W1[0:64]  (33.5 MB)
__device__ float g_qpos[NB * MQ * 3];

// ------------------------------------------------------------------
// Kernel 1: farthest point sampling, one CTA per cloud (serial chain)
// ------------------------------------------------------------------
__global__ void __launch_bounds__(1024, 1)
fps_kernel(const float* __restrict__ pos, float* __restrict__ dout, int extras)
{
    const int b   = blockIdx.x;
    const int tid = threadIdx.x;
    const int warp = tid >> 5, lane = tid & 31;
    const float* pb = pos + (size_t)b * NPB * 3;

    float px[8], py[8], pz[8], dmin[8];
    unsigned idc[8];
#pragma unroll
    for (int k = 0; k < 8; k++) {
        int i = tid + k * 1024;
        px[k] = pb[i * 3 + 0];
        py[k] = pb[i * 3 + 1];
        pz[k] = pb[i * 3 + 2];
        dmin[k] = 3.4e38f;
        idc[k] = (unsigned)(NPB - 1 - i);
    }

    __shared__ float sq[3];
    __shared__ unsigned long long wk[32];

    const long long OQ = (long long)NB * MQ * CDIM;
    const long long OB = OQ + (long long)NB * MQ * 3;
    const long long OI = OB + (long long)NB * MQ;

    // emit sample m = 0 (deterministic start at local index 0)
    if (tid == 0) {
        float qx = pb[0], qy = pb[1], qz = pb[2];
        sq[0] = qx; sq[1] = qy; sq[2] = qz;
        int row = b * MQ + 0;
        g_qpos[row * 3 + 0] = qx; g_qpos[row * 3 + 1] = qy; g_qpos[row * 3 + 2] = qz;
        if (extras) {
            dout[OQ + row * 3 + 0] = qx;
            dout[OQ + row * 3 + 1] = qy;
            dout[OQ + row * 3 + 2] = qz;
            dout[OB + row] = (float)b;
            dout[OI + row] = (float)(b * NPB + 0);
        }
    }
    __syncthreads();

    for (int m = 1; m < MQ; m++) {
        float qx = sq[0], qy = sq[1], qz = sq[2];
        unsigned long long best = 0ull;
#pragma unroll
        for (int k = 0; k < 8; k++) {
            float dx = px[k] - qx, dy = py[k] - qy, dz = pz[k] - qz;
            // match XLA fp-contraction order: ((dx*dx + dy*dy) + dz*dz)
            float d2 = fmaf(dz, dz, fmaf(dy, dy, dx * dx));
            float dm = fminf(dmin[k], d2);
            dmin[k] = dm;
            unsigned long long key =
                ((unsigned long long)__float_as_uint(dm) << 32) | (unsigned long long)idc[k];
            best = (key > best) ? key : best;
        }
#pragma unroll
        for (int s = 16; s > 0; s >>= 1) {
            unsigned long long o = __shfl_xor_sync(0xffffffffu, best, s);
            best = (o > best) ? o : best;
        }
        if (lane == 0) wk[warp] = best;
        __syncthreads();
        if (warp == 0) {
            unsigned long long v = wk[lane];
#pragma unroll
            for (int s = 16; s > 0; s >>= 1) {
                unsigned long long o = __shfl_xor_sync(0xffffffffu, v, s);
                v = (o > v) ? o : v;
            }
            if (lane == 0) {
                int win = NPB - 1 - (int)(v & 0xffffffffull);
                float qx2 = pb[win * 3 + 0], qy2 = pb[win * 3 + 1], qz2 = pb[win * 3 + 2];
                sq[0] = qx2; sq[1] = qy2; sq[2] = qz2;
                int row = b * MQ + m;
                g_qpos[row * 3 + 0] = qx2; g_qpos[row * 3 + 1] = qy2; g_qpos[row * 3 + 2] = qz2;
                if (extras) {
                    dout[OQ + row * 3 + 0] = qx2;
                    dout[OQ + row * 3 + 1] = qy2;
                    dout[OQ + row * 3 + 2] = qz2;
                    dout[OB + row] = (float)b;
                    dout[OI + row] = (float)(b * NPB + win);
                }
            }
        }
        __syncthreads();
    }
}

// ------------------------------------------------------------------
// Kernel 2: xW = x @ W1[0:64]   (65536 x 64 x 128 GEMM, fp32)
// ------------------------------------------------------------------
__global__ void __launch_bounds__(256)
xw_kernel(const float* __restrict__ x, const float* __restrict__ W1)
{
    __shared__ float Wf[64 * CDIM];
    for (int i = threadIdx.x; i < 64 * CDIM / 4; i += 256)
        ((float4*)Wf)[i] = ((const float4*)W1)[i];
    __syncthreads();

    const int warp = threadIdx.x >> 5, lane = threadIdx.x & 31;
    const int rbase = blockIdx.x * 128 + warp * 16;

    for (int p = 0; p < 8; p++) {
        int r0 = rbase + p * 2, r1 = r0 + 1;
        float2 a = ((const float2*)(x + (size_t)r0 * FDIM))[lane];
        float2 c = ((const float2*)(x + (size_t)r1 * FDIM))[lane];
        float4 a0 = make_float4(0.f, 0.f, 0.f, 0.f);
        float4 a1 = make_float4(0.f, 0.f, 0.f, 0.f);
#pragma unroll
        for (int k2 = 0; k2 < 32; k2++) {
            float xa0 = __shfl_sync(0xffffffffu, a.x, k2);
            float xa1 = __shfl_sync(0xffffffffu, a.y, k2);
            float xc0 = __shfl_sync(0xffffffffu, c.x, k2);
            float xc1 = __shfl_sync(0xffffffffu, c.y, k2);
            float4 w0 = ((float4*)(Wf + (2 * k2) * CDIM))[lane];
            float4 w1 = ((float4*)(Wf + (2 * k2 + 1) * CDIM))[lane];
            a0.x = fmaf(xa0, w0.x, a0.x); a0.y = fmaf(xa0, w0.y, a0.y);
            a0.z = fmaf(xa0, w0.z, a0.z); a0.w = fmaf(xa0, w0.w, a0.w);
            a0.x = fmaf(xa1, w1.x, a0.x); a0.y = fmaf(xa1, w1.y, a0.y);
            a0.z = fmaf(xa1, w1.z, a0.z); a0.w = fmaf(xa1, w1.w, a0.w);
            a1.x = fmaf(xc0, w0.x, a1.x); a1.y = fmaf(xc0, w0.y, a1.y);
            a1.z = fmaf(xc0, w0.z, a1.z); a1.w = fmaf(xc0, w0.w, a1.w);
            a1.x = fmaf(xc1, w1.x, a1.x); a1.y = fmaf(xc1, w1.y, a1.y);
            a1.z = fmaf(xc1, w1.z, a1.z); a1.w = fmaf(xc1, w1.w, a1.w);
        }
        ((float4*)(g_xw + (size_t)r0 * CDIM))[lane] = a0;
        ((float4*)(g_xw + (size_t)r1 * CDIM))[lane] = a1;
    }
}

// ------------------------------------------------------------------
// Kernel 3: ball query (exact top-K set) + fused pos-MLP + max + relu
// grid (16, NB), 512 threads (16 warps); each warp: 8 queries
// ------------------------------------------------------------------
__global__ void __launch_bounds__(512)
ballconv_kernel(const float* __restrict__ pos, const float* __restrict__ W1,
                const float* __restrict__ b1, float* __restrict__ dout)
{
    extern __shared__ float smem[];
    float* spx = smem;
    float* spy = spx + NPB;
    float* spz = spy + NPB;
    unsigned long long* skey = (unsigned long long*)(spz + NPB);   // 16 warps * CAP
    int* ssel = (int*)(skey + 16 * CAP);                           // 16 warps * KNN

    const int b = blockIdx.y;
    const int tid = threadIdx.x, warp = tid >> 5, lane = tid & 31;
    const float* pb = pos + (size_t)b * NPB * 3;

    for (int i = tid; i < NPB * 3; i += 512) {
        float v = pb[i];
        int pt = i / 3, c = i - pt * 3;
        if (c == 0) spx[pt] = v; else if (c == 1) spy[pt] = v; else spz[pt] = v;
    }

    // this lane's 4 channels of the pos-part weights + bias
    float4 wp0 = *(const float4*)(W1 + 64 * CDIM + 4 * lane);
    float4 wp1 = *(const float4*)(W1 + 65 * CDIM + 4 * lane);
    float4 wp2 = *(const float4*)(W1 + 66 * CDIM + 4 * lane);
    float4 bb  = *(const float4*)(b1 + 4 * lane);
    __syncthreads();

    unsigned long long* mykey = skey + warp * CAP;
    int* mysel = ssel + warp * KNN;
    const unsigned ltmask = (1u << lane) - 1u;
    const int qbase = blockIdx.x * (MQ / 16) + warp * 8;

    for (int qi = 0; qi < 8; qi++) {
        int m = qbase + qi;
        int row = b * MQ + m;
        float qx = g_qpos[row * 3 + 0];
        float qy = g_qpos[row * 3 + 1];
        float qz = g_qpos[row * 3 + 2];

        // scan cloud, collect candidates within radius
        int cnt = 0;
        for (int t = 0; t < NPB / 32; t++) {
            int i = lane + t * 32;
            float dx = spx[i] - qx, dy = spy[i] - qy, dz = spz[i] - qz;
            float d2 = fmaf(dz, dz, fmaf(dy, dy, dx * dx));
            bool in = (d2 <= R2C);
            unsigned mk = __ballot_sync(0xffffffffu, in);
            if (in) {
                int off = cnt + __popc(mk & ltmask);
                if (off < CAP)
                    mykey[off] = ((unsigned long long)__float_as_uint(d2) << 32) | (unsigned)i;
            }
            cnt += __popc(mk);
        }
        if (cnt > CAP) cnt = CAP;

        // select K smallest (d2, idx) — exact top_k set semantics
        int nsel;
        if (cnt <= KNN) {
            nsel = cnt;
            if (lane < cnt) mysel[lane] = (int)(mykey[lane] & 0xffffffffull);
        } else {
            nsel = KNN;
            int written = 0;
            for (int base = 0; base < cnt; base += 32) {
                int c = base + lane;
                bool s = false;
                unsigned long long ka = 0ull;
                if (c < cnt) {
                    ka = mykey[c];
                    int rank = 0;
                    for (int e = 0; e < cnt; e++) rank += (mykey[e] < ka) ? 1 : 0;
                    s = (rank < KNN);
                }
                unsigned mk = __ballot_sync(0xffffffffu, s);
                if (s) mysel[written + __popc(mk & ltmask)] = (int)(ka & 0xffffffffull);
                written += __popc(mk);
            }
        }
        __syncwarp();

        // conv: max over neighbors of xW[j] + (p_j - p_i) . Wpos, then +b, relu
        float4 vm = make_float4(-3.4e38f, -3.4e38f, -3.4e38f, -3.4e38f);
        for (int s = 0; s < nsel; s++) {
            int j = mysel[s];
            float dx = spx[j] - qx, dy = spy[j] - qy, dz = spz[j] - qz;
            float4 xw = *(const float4*)(g_xw + (size_t)(b * NPB + j) * CDIM + 4 * lane);
            float v0 = fmaf(dz, wp2.x, fmaf(dy, wp1.x, fmaf(dx, wp0.x, xw.x)));
            float v1 = fmaf(dz, wp2.y, fmaf(dy, wp1.y, fmaf(dx, wp0.y, xw.y)));
            float v2 = fmaf(dz, wp2.z, fmaf(dy, wp1.z, fmaf(dx, wp0.z, xw.z)));
            float v3 = fmaf(dz, wp2.w, fmaf(dy, wp1.w, fmaf(dx, wp0.w, xw.w)));
            vm.x = fmaxf(vm.x, v0); vm.y = fmaxf(vm.y, v1);
            vm.z = fmaxf(vm.z, v2); vm.w = fmaxf(vm.w, v3);
        }
        float4 o;
        o.x = fmaxf(vm.x + bb.x, 0.0f);
        o.y = fmaxf(vm.y + bb.y, 0.0f);
        o.z = fmaxf(vm.z + bb.z, 0.0f);
        o.w = fmaxf(vm.w + bb.w, 0.0f);
        *(float4*)(dout + (size_t)row * CDIM + 4 * lane) = o;
        __syncwarp();
    }
}

// ------------------------------------------------------------------
extern "C" void kernel_launch(void* const* d_in, const int* in_sizes, int n_in,
                              void* d_out, int out_size)
{
    const float *x = nullptr, *pos = nullptr, *W1 = nullptr, *b1 = nullptr;
    for (int i = 0; i < n_in; i++) {
        switch (in_sizes[i]) {
            case NROWS * FDIM:      x   = (const float*)d_in[i]; break;  // 4194304
            case NROWS * 3:         pos = (const float*)d_in[i]; break;  // 196608
            case (FDIM + 3) * CDIM: W1  = (const float*)d_in[i]; break;  // 8576
            case CDIM:              b1  = (const float*)d_in[i]; break;  // 128
            default: break;                                              // batch (unused)
        }
    }
    float* out = (float*)d_out;
    long long total = (long long)NB * MQ * CDIM + (long long)NB * MQ * 3 + 2ll * NB * MQ;
    int extras = ((long long)out_size >= total) ? 1 : 0;

    xw_kernel<<<512, 256>>>(x, W1);
    fps_kernel<<<NB, 1024>>>(pos, out, extras);

    size_t smem = (size_t)3 * NPB * 4 + (size_t)16 * CAP * 8 + (size_t)16 * KNN * 4; // 133120
    cudaFuncSetAttribute(ballconv_kernel, cudaFuncAttributeMaxDynamicSharedMemorySize, (int)smem);
    ballconv_kernel<<<dim3(16, NB), 512, smem>>>(pos, W1, b1, out);
}